// round 1
// baseline (speedup 1.0000x reference)
#include <cuda_runtime.h>
#include <math.h>

// Problem constants
#define Bq 8
#define Sq 2048
#define Eq 128
#define Hq 8
#define HSq 16
#define BSROWS (Bq * Sq)  // 16384

// Scratch (device globals — no allocation allowed)
__device__ float g_q[Bq * Hq * Sq * HSq];   // [b,h,s,d]
__device__ float g_k[Bq * Hq * Sq * HSq];
__device__ float g_v[Bq * Hq * Sq * HSq];
__device__ float g_a[BSROWS * Eq];          // attention output, [b*S+s, h*16+d]

// ---------------------------------------------------------------------------
// QKV projection GEMM: C[row, col] = sum_e x[row,e] * W[col,e]
// row in [0,16384), col in [0,128) where col = h*16+d, W row-major [128,128]
// Tile 64x64, 256 threads, 4x4 per thread, K=128 in two 64-chunks.
// Output written in attention layout [b,h,s,d]. grid (256, 2, 3): z picks q/k/v.
// ---------------------------------------------------------------------------
__global__ __launch_bounds__(256) void qkv_gemm(
    const float* __restrict__ A,
    const float* __restrict__ Wq,
    const float* __restrict__ Wk,
    const float* __restrict__ Wv)
{
    __shared__ float As[64][68];  // K-major, padded to keep float4 reads aligned
    __shared__ float Bs[64][68];

    const int tid = threadIdx.x;
    const int bm = blockIdx.x;
    const int bn = blockIdx.y;
    const int wz = blockIdx.z;

    const float* W = (wz == 0) ? Wq : ((wz == 1) ? Wk : Wv);
    float* Cout = (wz == 0) ? g_q : ((wz == 1) ? g_k : g_v);

    const int r  = tid & 63;   // smem row owner (conflict-free stores: r consecutive in warp)
    const int kc = tid >> 6;   // 0..3
    const int ty = tid >> 4;   // 0..15
    const int tx = tid & 15;   // 0..15

    float acc[4][4] = {};

    const float* Arow = A + (size_t)(bm * 64 + r) * 128;
    const float* Wrow = W + (size_t)(bn * 64 + r) * 128;

    #pragma unroll
    for (int ch = 0; ch < 2; ++ch) {
        #pragma unroll
        for (int i = 0; i < 4; ++i) {
            const int k0 = kc * 16 + i * 4;   // local k in chunk, 0..63
            float4 a4 = *(const float4*)&Arow[ch * 64 + k0];
            float4 b4 = *(const float4*)&Wrow[ch * 64 + k0];
            As[k0 + 0][r] = a4.x; As[k0 + 1][r] = a4.y;
            As[k0 + 2][r] = a4.z; As[k0 + 3][r] = a4.w;
            Bs[k0 + 0][r] = b4.x; Bs[k0 + 1][r] = b4.y;
            Bs[k0 + 2][r] = b4.z; Bs[k0 + 3][r] = b4.w;
        }
        __syncthreads();
        #pragma unroll
        for (int k = 0; k < 64; ++k) {
            float4 a4 = *(const float4*)&As[k][ty * 4];
            float4 b4 = *(const float4*)&Bs[k][tx * 4];
            const float av[4] = {a4.x, a4.y, a4.z, a4.w};
            const float bv[4] = {b4.x, b4.y, b4.z, b4.w};
            #pragma unroll
            for (int i = 0; i < 4; ++i)
                #pragma unroll
                for (int j = 0; j < 4; ++j)
                    acc[i][j] = fmaf(av[i], bv[j], acc[i][j]);
        }
        __syncthreads();
    }

    // Epilogue: scatter into [b,h,s,d]
    #pragma unroll
    for (int i = 0; i < 4; ++i) {
        const int row = bm * 64 + ty * 4 + i;
        const int b = row >> 11;          // /2048
        const int s = row & 2047;
        #pragma unroll
        for (int j = 0; j < 4; ++j) {
            const int col = bn * 64 + tx * 4 + j;
            const int h = col >> 4;
            const int d = col & 15;
            Cout[(((size_t)b * Hq + h) * Sq + s) * HSq + d] = acc[i][j];
        }
    }
}

// ---------------------------------------------------------------------------
// Flash-style attention per (b,h). One thread per query row, 128 queries/block.
// Streams K/V in 32-row tiles through smem. Scores scaled by *sqrt(16)=4
// (reference MULTIPLIES) — folded into q at load.
// grid (S/128, B*H), 128 threads.
// ---------------------------------------------------------------------------
__global__ __launch_bounds__(128) void attn_kernel()
{
    __shared__ float Ks[32][16];
    __shared__ float Vs[32][16];

    const int tid = threadIdx.x;
    const int bh = blockIdx.y;               // b*H + h
    const int s = blockIdx.x * 128 + tid;

    const float* qp = &g_q[((size_t)bh * Sq + s) * HSq];
    float q[16], o[16];
    #pragma unroll
    for (int d4 = 0; d4 < 4; ++d4) {
        float4 v = *(const float4*)&qp[d4 * 4];
        q[d4 * 4 + 0] = v.x * 4.0f;
        q[d4 * 4 + 1] = v.y * 4.0f;
        q[d4 * 4 + 2] = v.z * 4.0f;
        q[d4 * 4 + 3] = v.w * 4.0f;
    }
    #pragma unroll
    for (int d = 0; d < 16; ++d) o[d] = 0.0f;

    float m = -INFINITY;
    float l = 0.0f;

    const float4* Kg = (const float4*)&g_k[(size_t)bh * Sq * HSq];
    const float4* Vg = (const float4*)&g_v[(size_t)bh * Sq * HSq];
    float4* Ks4 = (float4*)Ks;
    float4* Vs4 = (float4*)Vs;

    for (int kt = 0; kt < Sq / 32; ++kt) {
        // cooperative tile load: 32 keys x 16 dims = 128 float4 each
        Ks4[tid] = Kg[kt * 128 + tid];
        Vs4[tid] = Vg[kt * 128 + tid];
        __syncthreads();

        float sc[32];
        float tmax = -INFINITY;
        #pragma unroll
        for (int j = 0; j < 32; ++j) {
            float a0 = 0.0f, a1 = 0.0f, a2 = 0.0f, a3 = 0.0f;
            #pragma unroll
            for (int d4 = 0; d4 < 4; ++d4) {
                float4 kv = *(const float4*)&Ks[j][d4 * 4];  // broadcast across threads
                a0 = fmaf(q[d4 * 4 + 0], kv.x, a0);
                a1 = fmaf(q[d4 * 4 + 1], kv.y, a1);
                a2 = fmaf(q[d4 * 4 + 2], kv.z, a2);
                a3 = fmaf(q[d4 * 4 + 3], kv.w, a3);
            }
            const float acc = (a0 + a1) + (a2 + a3);
            sc[j] = acc;
            tmax = fmaxf(tmax, acc);
        }

        const float mnew = fmaxf(m, tmax);
        const float corr = __expf(m - mnew);   // exp(-inf)=0 handles first tile
        l *= corr;
        #pragma unroll
        for (int d = 0; d < 16; ++d) o[d] *= corr;

        #pragma unroll
        for (int j = 0; j < 32; ++j) {
            const float p = __expf(sc[j] - mnew);
            l += p;
            #pragma unroll
            for (int d4 = 0; d4 < 4; ++d4) {
                float4 vv = *(const float4*)&Vs[j][d4 * 4];
                o[d4 * 4 + 0] = fmaf(p, vv.x, o[d4 * 4 + 0]);
                o[d4 * 4 + 1] = fmaf(p, vv.y, o[d4 * 4 + 1]);
                o[d4 * 4 + 2] = fmaf(p, vv.z, o[d4 * 4 + 2]);
                o[d4 * 4 + 3] = fmaf(p, vv.w, o[d4 * 4 + 3]);
            }
        }
        m = mnew;
        __syncthreads();
    }

    const float inv = 1.0f / l;
    const int b = bh >> 3;
    const int h = bh & 7;
    float* op = &g_a[((size_t)b * Sq + s) * Eq + h * HSq];
    #pragma unroll
    for (int d4 = 0; d4 < 4; ++d4) {
        float4 v;
        v.x = o[d4 * 4 + 0] * inv;
        v.y = o[d4 * 4 + 1] * inv;
        v.z = o[d4 * 4 + 2] * inv;
        v.w = o[d4 * 4 + 3] * inv;
        *(float4*)&op[d4 * 4] = v;
    }
}

// ---------------------------------------------------------------------------
// Output projection: out[row, col] = sum_e g_a[row,e] * Wp[col,e] + bp[col]
// Same tiling as qkv_gemm. grid (256, 2).
// ---------------------------------------------------------------------------
__global__ __launch_bounds__(256) void proj_gemm(
    const float* __restrict__ W,
    const float* __restrict__ bias,
    float* __restrict__ C)
{
    __shared__ float As[64][68];
    __shared__ float Bs[64][68];

    const int tid = threadIdx.x;
    const int bm = blockIdx.x;
    const int bn = blockIdx.y;

    const int r  = tid & 63;
    const int kc = tid >> 6;
    const int ty = tid >> 4;
    const int tx = tid & 15;

    float acc[4][4] = {};

    const float* Arow = g_a + (size_t)(bm * 64 + r) * 128;
    const float* Wrow = W + (size_t)(bn * 64 + r) * 128;

    #pragma unroll
    for (int ch = 0; ch < 2; ++ch) {
        #pragma unroll
        for (int i = 0; i < 4; ++i) {
            const int k0 = kc * 16 + i * 4;
            float4 a4 = *(const float4*)&Arow[ch * 64 + k0];
            float4 b4 = *(const float4*)&Wrow[ch * 64 + k0];
            As[k0 + 0][r] = a4.x; As[k0 + 1][r] = a4.y;
            As[k0 + 2][r] = a4.z; As[k0 + 3][r] = a4.w;
            Bs[k0 + 0][r] = b4.x; Bs[k0 + 1][r] = b4.y;
            Bs[k0 + 2][r] = b4.z; Bs[k0 + 3][r] = b4.w;
        }
        __syncthreads();
        #pragma unroll
        for (int k = 0; k < 64; ++k) {
            float4 a4 = *(const float4*)&As[k][ty * 4];
            float4 b4 = *(const float4*)&Bs[k][tx * 4];
            const float av[4] = {a4.x, a4.y, a4.z, a4.w};
            const float bv[4] = {b4.x, b4.y, b4.z, b4.w};
            #pragma unroll
            for (int i = 0; i < 4; ++i)
                #pragma unroll
                for (int j = 0; j < 4; ++j)
                    acc[i][j] = fmaf(av[i], bv[j], acc[i][j]);
        }
        __syncthreads();
    }

    #pragma unroll
    for (int i = 0; i < 4; ++i) {
        const int row = bm * 64 + ty * 4 + i;
        #pragma unroll
        for (int j = 0; j < 4; ++j) {
            const int col = bn * 64 + tx * 4 + j;
            C[(size_t)row * Eq + col] = acc[i][j] + bias[col];
        }
    }
}

// ---------------------------------------------------------------------------
// Launch. Inputs (metadata order): x, Wk, Wq, Wv, Wp, bp. Output: float32.
// ---------------------------------------------------------------------------
extern "C" void kernel_launch(void* const* d_in, const int* in_sizes, int n_in,
                              void* d_out, int out_size)
{
    const float* x  = (const float*)d_in[0];
    const float* Wk = (const float*)d_in[1];
    const float* Wq = (const float*)d_in[2];
    const float* Wv = (const float*)d_in[3];
    const float* Wp = (const float*)d_in[4];
    const float* bp = (const float*)d_in[5];
    float* out = (float*)d_out;

    qkv_gemm<<<dim3(BSROWS / 64, 2, 3), 256>>>(x, Wq, Wk, Wv);
    attn_kernel<<<dim3(Sq / 128, Bq * Hq), 128>>>();
    proj_gemm<<<dim3(BSROWS / 64, 2), 256>>>(Wp, bp, out);
}

// round 2
// speedup vs baseline: 1.5421x; 1.5421x over previous
#include <cuda_runtime.h>
#include <math.h>

// Problem constants
#define Bq 8
#define Sq 2048
#define Eq 128
#define Hq 8
#define HSq 16
#define BSROWS (Bq * Sq)  // 16384

typedef unsigned long long u64;

// ---- packed f32x2 helpers (FFMA2 path; ptxas never auto-fuses, PTX only) ----
__device__ __forceinline__ u64 pack2(float lo, float hi) {
    u64 r; asm("mov.b64 %0, {%1,%2};" : "=l"(r) : "f"(lo), "f"(hi)); return r;
}
__device__ __forceinline__ u64 fma2(u64 a, u64 b, u64 c) {
    u64 d; asm("fma.rn.f32x2 %0, %1, %2, %3;" : "=l"(d) : "l"(a), "l"(b), "l"(c)); return d;
}
__device__ __forceinline__ u64 add2(u64 a, u64 b) {
    u64 d; asm("add.rn.f32x2 %0, %1, %2;" : "=l"(d) : "l"(a), "l"(b)); return d;
}
__device__ __forceinline__ u64 mul2(u64 a, u64 b) {
    u64 d; asm("mul.rn.f32x2 %0, %1, %2;" : "=l"(d) : "l"(a), "l"(b)); return d;
}
__device__ __forceinline__ void unpack2(u64 v, float& lo, float& hi) {
    asm("mov.b64 {%0,%1}, %2;" : "=f"(lo), "=f"(hi) : "l"(v));
}

// Scratch (device globals — no allocation allowed)
__device__ float g_q[Bq * Hq * Sq * HSq];   // [b,h,s,d]
__device__ float g_k[Bq * Hq * Sq * HSq];
__device__ float g_v[Bq * Hq * Sq * HSq];
__device__ float g_a[BSROWS * Eq];          // attention output, [b*S+s, h*16+d]

// ---------------------------------------------------------------------------
// QKV projection GEMM, f32x2-packed mainloop.
// C[row, col] = sum_e x[row,e] * W[col,e]; output scattered to [b,h,s,d].
// ---------------------------------------------------------------------------
__global__ __launch_bounds__(256) void qkv_gemm(
    const float* __restrict__ A,
    const float* __restrict__ Wq,
    const float* __restrict__ Wk,
    const float* __restrict__ Wv)
{
    __shared__ float As[64][68];  // K-major, padded
    __shared__ float Bs[64][68];

    const int tid = threadIdx.x;
    const int bm = blockIdx.x;
    const int bn = blockIdx.y;
    const int wz = blockIdx.z;

    const float* W = (wz == 0) ? Wq : ((wz == 1) ? Wk : Wv);
    float* Cout = (wz == 0) ? g_q : ((wz == 1) ? g_k : g_v);

    const int r  = tid & 63;
    const int kc = tid >> 6;
    const int ty = tid >> 4;
    const int tx = tid & 15;

    u64 acc2[4][2];
    #pragma unroll
    for (int i = 0; i < 4; ++i) { acc2[i][0] = 0ull; acc2[i][1] = 0ull; }

    const float* Arow = A + (size_t)(bm * 64 + r) * 128;
    const float* Wrow = W + (size_t)(bn * 64 + r) * 128;

    #pragma unroll
    for (int ch = 0; ch < 2; ++ch) {
        #pragma unroll
        for (int i = 0; i < 4; ++i) {
            const int k0 = kc * 16 + i * 4;
            float4 a4 = *(const float4*)&Arow[ch * 64 + k0];
            float4 b4 = *(const float4*)&Wrow[ch * 64 + k0];
            As[k0 + 0][r] = a4.x; As[k0 + 1][r] = a4.y;
            As[k0 + 2][r] = a4.z; As[k0 + 3][r] = a4.w;
            Bs[k0 + 0][r] = b4.x; Bs[k0 + 1][r] = b4.y;
            Bs[k0 + 2][r] = b4.z; Bs[k0 + 3][r] = b4.w;
        }
        __syncthreads();
        #pragma unroll
        for (int k = 0; k < 64; ++k) {
            float4 a4 = *(const float4*)&As[k][ty * 4];
            ulonglong2 b2 = *(const ulonglong2*)&Bs[k][tx * 4];
            u64 a0 = pack2(a4.x, a4.x);
            u64 a1 = pack2(a4.y, a4.y);
            u64 a2 = pack2(a4.z, a4.z);
            u64 a3 = pack2(a4.w, a4.w);
            acc2[0][0] = fma2(a0, b2.x, acc2[0][0]);
            acc2[0][1] = fma2(a0, b2.y, acc2[0][1]);
            acc2[1][0] = fma2(a1, b2.x, acc2[1][0]);
            acc2[1][1] = fma2(a1, b2.y, acc2[1][1]);
            acc2[2][0] = fma2(a2, b2.x, acc2[2][0]);
            acc2[2][1] = fma2(a2, b2.y, acc2[2][1]);
            acc2[3][0] = fma2(a3, b2.x, acc2[3][0]);
            acc2[3][1] = fma2(a3, b2.y, acc2[3][1]);
        }
        __syncthreads();
    }

    // Epilogue: scatter into [b,h,s,d]
    #pragma unroll
    for (int i = 0; i < 4; ++i) {
        const int row = bm * 64 + ty * 4 + i;
        const int b = row >> 11;
        const int s = row & 2047;
        float c[4];
        unpack2(acc2[i][0], c[0], c[1]);
        unpack2(acc2[i][1], c[2], c[3]);
        #pragma unroll
        for (int j = 0; j < 4; ++j) {
            const int col = bn * 64 + tx * 4 + j;
            const int h = col >> 4;
            const int d = col & 15;
            Cout[(((size_t)b * Hq + h) * Sq + s) * HSq + d] = c[j];
        }
    }
}

// ---------------------------------------------------------------------------
// Flash attention per (b,h): one thread per query, 256 queries/block.
// All inner math uses packed f32x2 (2 MACs per FMA-pipe issue).
// Reference MULTIPLIES scores by sqrt(16)=4 — folded into q at load.
// grid (S/256, B*H), 256 threads.
// ---------------------------------------------------------------------------
__global__ __launch_bounds__(256) void attn_kernel()
{
    __shared__ float Ks[32][16];
    __shared__ float Vs[32][16];

    const int tid = threadIdx.x;
    const int bh = blockIdx.y;
    const int s = blockIdx.x * 256 + tid;

    const float* qp = &g_q[((size_t)bh * Sq + s) * HSq];
    u64 q2[8], o2[8];
    #pragma unroll
    for (int i = 0; i < 4; ++i) {
        float4 v = *(const float4*)&qp[i * 4];
        q2[i * 2 + 0] = pack2(v.x * 4.0f, v.y * 4.0f);
        q2[i * 2 + 1] = pack2(v.z * 4.0f, v.w * 4.0f);
    }
    #pragma unroll
    for (int i = 0; i < 8; ++i) o2[i] = 0ull;

    float m = -INFINITY;
    float l = 0.0f;

    const float4* Kg = (const float4*)&g_k[(size_t)bh * Sq * HSq];
    const float4* Vg = (const float4*)&g_v[(size_t)bh * Sq * HSq];
    float4* Ks4 = (float4*)Ks;
    float4* Vs4 = (float4*)Vs;

    for (int kt = 0; kt < Sq / 32; ++kt) {
        // cooperative tile load: K tile = 128 float4, V tile = 128 float4
        if (tid < 128) Ks4[tid] = Kg[kt * 128 + tid];
        else           Vs4[tid - 128] = Vg[kt * 128 + (tid - 128)];
        __syncthreads();

        float sc[32];
        float tmax = -INFINITY;
        #pragma unroll
        for (int j = 0; j < 32; ++j) {
            const ulonglong2* kp = (const ulonglong2*)&Ks[j][0];  // 4 x LDS.128
            ulonglong2 k01 = kp[0], k23 = kp[1], k45 = kp[2], k67 = kp[3];
            u64 accA = fma2(q2[0], k01.x, 0ull);
            u64 accB = fma2(q2[1], k01.y, 0ull);
            accA = fma2(q2[2], k23.x, accA);
            accB = fma2(q2[3], k23.y, accB);
            accA = fma2(q2[4], k45.x, accA);
            accB = fma2(q2[5], k45.y, accB);
            accA = fma2(q2[6], k67.x, accA);
            accB = fma2(q2[7], k67.y, accB);
            u64 c = add2(accA, accB);
            float lo, hi;
            unpack2(c, lo, hi);
            const float acc = lo + hi;
            sc[j] = acc;
            tmax = fmaxf(tmax, acc);
        }

        const float mnew = fmaxf(m, tmax);
        const float corr = __expf(m - mnew);   // exp(-inf)=0 handles first tile
        l *= corr;
        const u64 corr2 = pack2(corr, corr);
        #pragma unroll
        for (int i = 0; i < 8; ++i) o2[i] = mul2(corr2, o2[i]);

        #pragma unroll
        for (int j = 0; j < 32; ++j) {
            const float p = __expf(sc[j] - mnew);
            l += p;
            const u64 p2 = pack2(p, p);
            const ulonglong2* vp = (const ulonglong2*)&Vs[j][0];
            ulonglong2 v01 = vp[0], v23 = vp[1], v45 = vp[2], v67 = vp[3];
            o2[0] = fma2(p2, v01.x, o2[0]);
            o2[1] = fma2(p2, v01.y, o2[1]);
            o2[2] = fma2(p2, v23.x, o2[2]);
            o2[3] = fma2(p2, v23.y, o2[3]);
            o2[4] = fma2(p2, v45.x, o2[4]);
            o2[5] = fma2(p2, v45.y, o2[5]);
            o2[6] = fma2(p2, v67.x, o2[6]);
            o2[7] = fma2(p2, v67.y, o2[7]);
        }
        m = mnew;
        __syncthreads();
    }

    const float inv = 1.0f / l;
    const int b = bh >> 3;
    const int h = bh & 7;
    float* op = &g_a[((size_t)b * Sq + s) * Eq + h * HSq];
    #pragma unroll
    for (int i = 0; i < 4; ++i) {
        float a0, a1, a2, a3;
        unpack2(o2[i * 2 + 0], a0, a1);
        unpack2(o2[i * 2 + 1], a2, a3);
        float4 v;
        v.x = a0 * inv; v.y = a1 * inv; v.z = a2 * inv; v.w = a3 * inv;
        *(float4*)&op[i * 4] = v;
    }
}

// ---------------------------------------------------------------------------
// Output projection, f32x2-packed mainloop. grid (256, 2).
// ---------------------------------------------------------------------------
__global__ __launch_bounds__(256) void proj_gemm(
    const float* __restrict__ W,
    const float* __restrict__ bias,
    float* __restrict__ C)
{
    __shared__ float As[64][68];
    __shared__ float Bs[64][68];

    const int tid = threadIdx.x;
    const int bm = blockIdx.x;
    const int bn = blockIdx.y;

    const int r  = tid & 63;
    const int kc = tid >> 6;
    const int ty = tid >> 4;
    const int tx = tid & 15;

    u64 acc2[4][2];
    #pragma unroll
    for (int i = 0; i < 4; ++i) { acc2[i][0] = 0ull; acc2[i][1] = 0ull; }

    const float* Arow = g_a + (size_t)(bm * 64 + r) * 128;
    const float* Wrow = W + (size_t)(bn * 64 + r) * 128;

    #pragma unroll
    for (int ch = 0; ch < 2; ++ch) {
        #pragma unroll
        for (int i = 0; i < 4; ++i) {
            const int k0 = kc * 16 + i * 4;
            float4 a4 = *(const float4*)&Arow[ch * 64 + k0];
            float4 b4 = *(const float4*)&Wrow[ch * 64 + k0];
            As[k0 + 0][r] = a4.x; As[k0 + 1][r] = a4.y;
            As[k0 + 2][r] = a4.z; As[k0 + 3][r] = a4.w;
            Bs[k0 + 0][r] = b4.x; Bs[k0 + 1][r] = b4.y;
            Bs[k0 + 2][r] = b4.z; Bs[k0 + 3][r] = b4.w;
        }
        __syncthreads();
        #pragma unroll
        for (int k = 0; k < 64; ++k) {
            float4 a4 = *(const float4*)&As[k][ty * 4];
            ulonglong2 b2 = *(const ulonglong2*)&Bs[k][tx * 4];
            u64 a0 = pack2(a4.x, a4.x);
            u64 a1 = pack2(a4.y, a4.y);
            u64 a2 = pack2(a4.z, a4.z);
            u64 a3 = pack2(a4.w, a4.w);
            acc2[0][0] = fma2(a0, b2.x, acc2[0][0]);
            acc2[0][1] = fma2(a0, b2.y, acc2[0][1]);
            acc2[1][0] = fma2(a1, b2.x, acc2[1][0]);
            acc2[1][1] = fma2(a1, b2.y, acc2[1][1]);
            acc2[2][0] = fma2(a2, b2.x, acc2[2][0]);
            acc2[2][1] = fma2(a2, b2.y, acc2[2][1]);
            acc2[3][0] = fma2(a3, b2.x, acc2[3][0]);
            acc2[3][1] = fma2(a3, b2.y, acc2[3][1]);
        }
        __syncthreads();
    }

    #pragma unroll
    for (int i = 0; i < 4; ++i) {
        const int row = bm * 64 + ty * 4 + i;
        float c[4];
        unpack2(acc2[i][0], c[0], c[1]);
        unpack2(acc2[i][1], c[2], c[3]);
        #pragma unroll
        for (int j = 0; j < 4; ++j) {
            const int col = bn * 64 + tx * 4 + j;
            C[(size_t)row * Eq + col] = c[j] + bias[col];
        }
    }
}

// ---------------------------------------------------------------------------
// Launch. Inputs (metadata order): x, Wk, Wq, Wv, Wp, bp. Output: float32.
// ---------------------------------------------------------------------------
extern "C" void kernel_launch(void* const* d_in, const int* in_sizes, int n_in,
                              void* d_out, int out_size)
{
    const float* x  = (const float*)d_in[0];
    const float* Wk = (const float*)d_in[1];
    const float* Wq = (const float*)d_in[2];
    const float* Wv = (const float*)d_in[3];
    const float* Wp = (const float*)d_in[4];
    const float* bp = (const float*)d_in[5];
    float* out = (float*)d_out;

    qkv_gemm<<<dim3(BSROWS / 64, 2, 3), 256>>>(x, Wq, Wk, Wv);
    attn_kernel<<<dim3(Sq / 256, Bq * Hq), 256>>>();
    proj_gemm<<<dim3(BSROWS / 64, 2), 256>>>(Wp, bp, out);
}

// round 3
// speedup vs baseline: 1.5937x; 1.0335x over previous
#include <cuda_runtime.h>
#include <math.h>

// Problem constants
#define Bq 8
#define Sq 2048
#define Eq 128
#define Hq 8
#define HSq 16
#define BSROWS (Bq * Sq)  // 16384

typedef unsigned long long u64;

// ---- packed f32x2 helpers ----
__device__ __forceinline__ u64 pack2(float lo, float hi) {
    u64 r; asm("mov.b64 %0, {%1,%2};" : "=l"(r) : "f"(lo), "f"(hi)); return r;
}
__device__ __forceinline__ u64 fma2(u64 a, u64 b, u64 c) {
    u64 d; asm("fma.rn.f32x2 %0, %1, %2, %3;" : "=l"(d) : "l"(a), "l"(b), "l"(c)); return d;
}
__device__ __forceinline__ u64 add2(u64 a, u64 b) {
    u64 d; asm("add.rn.f32x2 %0, %1, %2;" : "=l"(d) : "l"(a), "l"(b)); return d;
}
__device__ __forceinline__ u64 mul2(u64 a, u64 b) {
    u64 d; asm("mul.rn.f32x2 %0, %1, %2;" : "=l"(d) : "l"(a), "l"(b)); return d;
}
__device__ __forceinline__ void unpack2(u64 v, float& lo, float& hi) {
    asm("mov.b64 {%0,%1}, %2;" : "=f"(lo), "=f"(hi) : "l"(v));
}
__device__ __forceinline__ float ex2(float x) {
    float y; asm("ex2.approx.f32 %0, %1;" : "=f"(y) : "f"(x)); return y;
}

// 4 * log2(e): reference multiplies scores by sqrt(16)=4; we fold that and the
// exp->exp2 conversion into q at load. Softmax is invariant to the log-base.
#define QSCALE 5.770780163555854f

// Scratch (device globals — no allocation allowed)
__device__ float g_q[Bq * Hq * Sq * HSq];   // [b,h,s,d]
__device__ float g_k[Bq * Hq * Sq * HSq];
__device__ float g_v[Bq * Hq * Sq * HSq];
__device__ float g_a[BSROWS * Eq];          // attention output, [b*S+s, h*16+d]

// ---------------------------------------------------------------------------
// QKV projection GEMM, f32x2-packed mainloop + global prefetch.
// ---------------------------------------------------------------------------
__global__ __launch_bounds__(256) void qkv_gemm(
    const float* __restrict__ A,
    const float* __restrict__ Wq,
    const float* __restrict__ Wk,
    const float* __restrict__ Wv)
{
    __shared__ float As[64][68];
    __shared__ float Bs[64][68];

    const int tid = threadIdx.x;
    const int bm = blockIdx.x;
    const int bn = blockIdx.y;
    const int wz = blockIdx.z;

    const float* W = (wz == 0) ? Wq : ((wz == 1) ? Wk : Wv);
    float* Cout = (wz == 0) ? g_q : ((wz == 1) ? g_k : g_v);

    const int r  = tid & 63;
    const int kc = tid >> 6;
    const int ty = tid >> 4;
    const int tx = tid & 15;

    u64 acc2[4][2];
    #pragma unroll
    for (int i = 0; i < 4; ++i) { acc2[i][0] = 0ull; acc2[i][1] = 0ull; }

    const float* Arow = A + (size_t)(bm * 64 + r) * 128;
    const float* Wrow = W + (size_t)(bn * 64 + r) * 128;

    float4 pa[4], pb[4];
    #pragma unroll
    for (int i = 0; i < 4; ++i) {
        const int k0 = kc * 16 + i * 4;
        pa[i] = *(const float4*)&Arow[k0];
        pb[i] = *(const float4*)&Wrow[k0];
    }

    #pragma unroll
    for (int ch = 0; ch < 2; ++ch) {
        #pragma unroll
        for (int i = 0; i < 4; ++i) {
            const int k0 = kc * 16 + i * 4;
            As[k0 + 0][r] = pa[i].x; As[k0 + 1][r] = pa[i].y;
            As[k0 + 2][r] = pa[i].z; As[k0 + 3][r] = pa[i].w;
            Bs[k0 + 0][r] = pb[i].x; Bs[k0 + 1][r] = pb[i].y;
            Bs[k0 + 2][r] = pb[i].z; Bs[k0 + 3][r] = pb[i].w;
        }
        __syncthreads();
        if (ch == 0) {
            #pragma unroll
            for (int i = 0; i < 4; ++i) {
                const int k0 = 64 + kc * 16 + i * 4;
                pa[i] = *(const float4*)&Arow[k0];
                pb[i] = *(const float4*)&Wrow[k0];
            }
        }
        #pragma unroll
        for (int k = 0; k < 64; ++k) {
            float4 a4 = *(const float4*)&As[k][ty * 4];
            ulonglong2 b2 = *(const ulonglong2*)&Bs[k][tx * 4];
            u64 a0 = pack2(a4.x, a4.x);
            u64 a1 = pack2(a4.y, a4.y);
            u64 a2 = pack2(a4.z, a4.z);
            u64 a3 = pack2(a4.w, a4.w);
            acc2[0][0] = fma2(a0, b2.x, acc2[0][0]);
            acc2[0][1] = fma2(a0, b2.y, acc2[0][1]);
            acc2[1][0] = fma2(a1, b2.x, acc2[1][0]);
            acc2[1][1] = fma2(a1, b2.y, acc2[1][1]);
            acc2[2][0] = fma2(a2, b2.x, acc2[2][0]);
            acc2[2][1] = fma2(a2, b2.y, acc2[2][1]);
            acc2[3][0] = fma2(a3, b2.x, acc2[3][0]);
            acc2[3][1] = fma2(a3, b2.y, acc2[3][1]);
        }
        __syncthreads();
    }

    #pragma unroll
    for (int i = 0; i < 4; ++i) {
        const int row = bm * 64 + ty * 4 + i;
        const int b = row >> 11;
        const int s = row & 2047;
        float c[4];
        unpack2(acc2[i][0], c[0], c[1]);
        unpack2(acc2[i][1], c[2], c[3]);
        #pragma unroll
        for (int j = 0; j < 4; ++j) {
            const int col = bn * 64 + tx * 4 + j;
            const int h = col >> 4;
            const int d = col & 15;
            Cout[(((size_t)b * Hq + h) * Sq + s) * HSq + d] = c[j];
        }
    }
}

// ---------------------------------------------------------------------------
// Flash attention per (b,h): one thread per query, 256 queries/block.
// K tile stored key-pair-interleaved: Kt[jp][d] = (K[2jp][d], K[2jp+1][d]),
// so one FFMA2 chain yields two key scores with no horizontal reduction.
// Scores in log2 domain (QSCALE folded into q); exp via ex2.approx.
// grid (S/256, B*H), 256 threads.
// ---------------------------------------------------------------------------
__global__ __launch_bounds__(256) void attn_kernel()
{
    __shared__ float Kt[16 * 32];   // [jp][d][pair], row = 32 floats = 128B
    __shared__ float Vs[32][16];

    const int tid = threadIdx.x;
    const int bh = blockIdx.y;
    const int s = blockIdx.x * 256 + tid;

    const float* qp = &g_q[((size_t)bh * Sq + s) * HSq];
    u64 qd2[16];   // (q[d], q[d]) duplicated
    #pragma unroll
    for (int i = 0; i < 4; ++i) {
        float4 v = *(const float4*)&qp[i * 4];
        qd2[i * 4 + 0] = pack2(v.x * QSCALE, v.x * QSCALE);
        qd2[i * 4 + 1] = pack2(v.y * QSCALE, v.y * QSCALE);
        qd2[i * 4 + 2] = pack2(v.z * QSCALE, v.z * QSCALE);
        qd2[i * 4 + 3] = pack2(v.w * QSCALE, v.w * QSCALE);
    }
    u64 o2[8];
    #pragma unroll
    for (int i = 0; i < 8; ++i) o2[i] = 0ull;

    float m = -INFINITY;
    u64 l2 = 0ull;

    const float4* Kg = (const float4*)&g_k[(size_t)bh * Sq * HSq];
    const float4* Vg = (const float4*)&g_v[(size_t)bh * Sq * HSq];
    float4* Vs4 = (float4*)Vs;

    // loader roles: tid<128 -> K, else V. Each owns one float4 per tile.
    const int lj  = tid >> 2;          // key index 0..31 (K loaders)
    const int ld0 = (tid & 3) * 4;     // dim start
    const int ljp = lj >> 1;
    const int lpar = lj & 1;

    float4 pf = (tid < 128) ? Kg[tid] : Vg[tid - 128];

    for (int kt = 0; kt < Sq / 32; ++kt) {
        if (tid < 128) {
            float* dst = &Kt[ljp * 32 + ld0 * 2 + lpar];
            dst[0] = pf.x; dst[2] = pf.y; dst[4] = pf.z; dst[6] = pf.w;
        } else {
            Vs4[tid - 128] = pf;
        }
        __syncthreads();
        if (kt + 1 < Sq / 32) {
            pf = (tid < 128) ? Kg[(kt + 1) * 128 + tid]
                             : Vg[(kt + 1) * 128 + (tid - 128)];
        }

        // --- scores: 16 key-pairs, packed over keys ---
        u64 sc2[16];
        float tmax = -INFINITY;
        #pragma unroll
        for (int jp = 0; jp < 16; ++jp) {
            const ulonglong2* kp = (const ulonglong2*)&Kt[jp * 32];
            ulonglong2 k0 = kp[0], k1 = kp[1], k2 = kp[2], k3 = kp[3];
            ulonglong2 k4 = kp[4], k5 = kp[5], k6 = kp[6], k7 = kp[7];
            u64 acc = fma2(qd2[0], k0.x, 0ull);
            acc = fma2(qd2[1],  k0.y, acc);
            acc = fma2(qd2[2],  k1.x, acc);
            acc = fma2(qd2[3],  k1.y, acc);
            acc = fma2(qd2[4],  k2.x, acc);
            acc = fma2(qd2[5],  k2.y, acc);
            acc = fma2(qd2[6],  k3.x, acc);
            acc = fma2(qd2[7],  k3.y, acc);
            acc = fma2(qd2[8],  k4.x, acc);
            acc = fma2(qd2[9],  k4.y, acc);
            acc = fma2(qd2[10], k5.x, acc);
            acc = fma2(qd2[11], k5.y, acc);
            acc = fma2(qd2[12], k6.x, acc);
            acc = fma2(qd2[13], k6.y, acc);
            acc = fma2(qd2[14], k7.x, acc);
            acc = fma2(qd2[15], k7.y, acc);
            sc2[jp] = acc;
            float s0, s1;
            unpack2(acc, s0, s1);
            tmax = fmaxf(tmax, fmaxf(s0, s1));
        }

        const float mnew = fmaxf(m, tmax);
        const float corr = ex2(m - mnew);   // ex2(-inf)=0 handles first tile
        const u64 corr2 = pack2(corr, corr);
        l2 = mul2(corr2, l2);
        #pragma unroll
        for (int i = 0; i < 8; ++i) o2[i] = mul2(corr2, o2[i]);

        #pragma unroll
        for (int jp = 0; jp < 16; ++jp) {
            float s0, s1;
            unpack2(sc2[jp], s0, s1);
            const float p0 = ex2(s0 - mnew);
            const float p1 = ex2(s1 - mnew);
            l2 = add2(l2, pack2(p0, p1));
            const u64 pa = pack2(p0, p0);
            const u64 pb = pack2(p1, p1);
            const ulonglong2* va = (const ulonglong2*)&Vs[2 * jp][0];
            ulonglong2 va0 = va[0], va1 = va[1], va2 = va[2], va3 = va[3];
            o2[0] = fma2(pa, va0.x, o2[0]);
            o2[1] = fma2(pa, va0.y, o2[1]);
            o2[2] = fma2(pa, va1.x, o2[2]);
            o2[3] = fma2(pa, va1.y, o2[3]);
            o2[4] = fma2(pa, va2.x, o2[4]);
            o2[5] = fma2(pa, va2.y, o2[5]);
            o2[6] = fma2(pa, va3.x, o2[6]);
            o2[7] = fma2(pa, va3.y, o2[7]);
            const ulonglong2* vb = (const ulonglong2*)&Vs[2 * jp + 1][0];
            ulonglong2 vb0 = vb[0], vb1 = vb[1], vb2 = vb[2], vb3 = vb[3];
            o2[0] = fma2(pb, vb0.x, o2[0]);
            o2[1] = fma2(pb, vb0.y, o2[1]);
            o2[2] = fma2(pb, vb1.x, o2[2]);
            o2[3] = fma2(pb, vb1.y, o2[3]);
            o2[4] = fma2(pb, vb2.x, o2[4]);
            o2[5] = fma2(pb, vb2.y, o2[5]);
            o2[6] = fma2(pb, vb3.x, o2[6]);
            o2[7] = fma2(pb, vb3.y, o2[7]);
        }
        m = mnew;
        __syncthreads();
    }

    float la, lb;
    unpack2(l2, la, lb);
    const float inv = 1.0f / (la + lb);
    const int b = bh >> 3;
    const int h = bh & 7;
    float* op = &g_a[((size_t)b * Sq + s) * Eq + h * HSq];
    #pragma unroll
    for (int i = 0; i < 4; ++i) {
        float a0, a1, a2, a3;
        unpack2(o2[i * 2 + 0], a0, a1);
        unpack2(o2[i * 2 + 1], a2, a3);
        float4 v;
        v.x = a0 * inv; v.y = a1 * inv; v.z = a2 * inv; v.w = a3 * inv;
        *(float4*)&op[i * 4] = v;
    }
}

// ---------------------------------------------------------------------------
// Output projection, f32x2-packed mainloop + prefetch. grid (256, 2).
// ---------------------------------------------------------------------------
__global__ __launch_bounds__(256) void proj_gemm(
    const float* __restrict__ W,
    const float* __restrict__ bias,
    float* __restrict__ C)
{
    __shared__ float As[64][68];
    __shared__ float Bs[64][68];

    const int tid = threadIdx.x;
    const int bm = blockIdx.x;
    const int bn = blockIdx.y;

    const int r  = tid & 63;
    const int kc = tid >> 6;
    const int ty = tid >> 4;
    const int tx = tid & 15;

    u64 acc2[4][2];
    #pragma unroll
    for (int i = 0; i < 4; ++i) { acc2[i][0] = 0ull; acc2[i][1] = 0ull; }

    const float* Arow = g_a + (size_t)(bm * 64 + r) * 128;
    const float* Wrow = W + (size_t)(bn * 64 + r) * 128;

    float4 pa[4], pb[4];
    #pragma unroll
    for (int i = 0; i < 4; ++i) {
        const int k0 = kc * 16 + i * 4;
        pa[i] = *(const float4*)&Arow[k0];
        pb[i] = *(const float4*)&Wrow[k0];
    }

    #pragma unroll
    for (int ch = 0; ch < 2; ++ch) {
        #pragma unroll
        for (int i = 0; i < 4; ++i) {
            const int k0 = kc * 16 + i * 4;
            As[k0 + 0][r] = pa[i].x; As[k0 + 1][r] = pa[i].y;
            As[k0 + 2][r] = pa[i].z; As[k0 + 3][r] = pa[i].w;
            Bs[k0 + 0][r] = pb[i].x; Bs[k0 + 1][r] = pb[i].y;
            Bs[k0 + 2][r] = pb[i].z; Bs[k0 + 3][r] = pb[i].w;
        }
        __syncthreads();
        if (ch == 0) {
            #pragma unroll
            for (int i = 0; i < 4; ++i) {
                const int k0 = 64 + kc * 16 + i * 4;
                pa[i] = *(const float4*)&Arow[k0];
                pb[i] = *(const float4*)&Wrow[k0];
            }
        }
        #pragma unroll
        for (int k = 0; k < 64; ++k) {
            float4 a4 = *(const float4*)&As[k][ty * 4];
            ulonglong2 b2 = *(const ulonglong2*)&Bs[k][tx * 4];
            u64 a0 = pack2(a4.x, a4.x);
            u64 a1 = pack2(a4.y, a4.y);
            u64 a2 = pack2(a4.z, a4.z);
            u64 a3 = pack2(a4.w, a4.w);
            acc2[0][0] = fma2(a0, b2.x, acc2[0][0]);
            acc2[0][1] = fma2(a0, b2.y, acc2[0][1]);
            acc2[1][0] = fma2(a1, b2.x, acc2[1][0]);
            acc2[1][1] = fma2(a1, b2.y, acc2[1][1]);
            acc2[2][0] = fma2(a2, b2.x, acc2[2][0]);
            acc2[2][1] = fma2(a2, b2.y, acc2[2][1]);
            acc2[3][0] = fma2(a3, b2.x, acc2[3][0]);
            acc2[3][1] = fma2(a3, b2.y, acc2[3][1]);
        }
        __syncthreads();
    }

    #pragma unroll
    for (int i = 0; i < 4; ++i) {
        const int row = bm * 64 + ty * 4 + i;
        float c[4];
        unpack2(acc2[i][0], c[0], c[1]);
        unpack2(acc2[i][1], c[2], c[3]);
        #pragma unroll
        for (int j = 0; j < 4; ++j) {
            const int col = bn * 64 + tx * 4 + j;
            C[(size_t)row * Eq + col] = c[j] + bias[col];
        }
    }
}

// ---------------------------------------------------------------------------
// Launch. Inputs (metadata order): x, Wk, Wq, Wv, Wp, bp. Output: float32.
// ---------------------------------------------------------------------------
extern "C" void kernel_launch(void* const* d_in, const int* in_sizes, int n_in,
                              void* d_out, int out_size)
{
    const float* x  = (const float*)d_in[0];
    const float* Wk = (const float*)d_in[1];
    const float* Wq = (const float*)d_in[2];
    const float* Wv = (const float*)d_in[3];
    const float* Wp = (const float*)d_in[4];
    const float* bp = (const float*)d_in[5];
    float* out = (float*)d_out;

    qkv_gemm<<<dim3(BSROWS / 64, 2, 3), 256>>>(x, Wq, Wk, Wv);
    attn_kernel<<<dim3(Sq / 256, Bq * Hq), 256>>>();
    proj_gemm<<<dim3(BSROWS / 64, 2), 256>>>(Wp, bp, out);
}

// round 4
// speedup vs baseline: 1.5951x; 1.0008x over previous
#include <cuda_runtime.h>
#include <math.h>

// Problem constants
#define Bq 8
#define Sq 2048
#define Eq 128
#define Hq 8
#define HSq 16
#define BSROWS (Bq * Sq)  // 16384

typedef unsigned long long u64;

// ---- packed f32x2 helpers ----
__device__ __forceinline__ u64 pack2(float lo, float hi) {
    u64 r; asm("mov.b64 %0, {%1,%2};" : "=l"(r) : "f"(lo), "f"(hi)); return r;
}
__device__ __forceinline__ u64 fma2(u64 a, u64 b, u64 c) {
    u64 d; asm("fma.rn.f32x2 %0, %1, %2, %3;" : "=l"(d) : "l"(a), "l"(b), "l"(c)); return d;
}
__device__ __forceinline__ u64 add2(u64 a, u64 b) {
    u64 d; asm("add.rn.f32x2 %0, %1, %2;" : "=l"(d) : "l"(a), "l"(b)); return d;
}
__device__ __forceinline__ u64 mul2(u64 a, u64 b) {
    u64 d; asm("mul.rn.f32x2 %0, %1, %2;" : "=l"(d) : "l"(a), "l"(b)); return d;
}
__device__ __forceinline__ void unpack2(u64 v, float& lo, float& hi) {
    asm("mov.b64 {%0,%1}, %2;" : "=f"(lo), "=f"(hi) : "l"(v));
}
__device__ __forceinline__ float ex2(float x) {
    float y; asm("ex2.approx.f32 %0, %1;" : "=f"(y) : "f"(x)); return y;
}

// 4 * log2(e): reference multiplies scores by sqrt(16)=4; we fold that and the
// exp->exp2 conversion into q at load. Softmax is invariant to the log-base.
#define QSCALE 5.770780163555854f

// Scratch (device globals — no allocation allowed)
__device__ float g_q[Bq * Hq * Sq * HSq];   // [b,h,s,d]
__device__ float g_k[Bq * Hq * Sq * HSq];
__device__ float g_v[Bq * Hq * Sq * HSq];
__device__ float g_a[BSROWS * Eq];          // attention output, [b*S+s, h*16+d]

// ---------------------------------------------------------------------------
// QKV projection GEMM, f32x2-packed mainloop + global prefetch.
// ---------------------------------------------------------------------------
__global__ __launch_bounds__(256) void qkv_gemm(
    const float* __restrict__ A,
    const float* __restrict__ Wq,
    const float* __restrict__ Wk,
    const float* __restrict__ Wv)
{
    __shared__ float As[64][68];
    __shared__ float Bs[64][68];

    const int tid = threadIdx.x;
    const int bm = blockIdx.x;
    const int bn = blockIdx.y;
    const int wz = blockIdx.z;

    const float* W = (wz == 0) ? Wq : ((wz == 1) ? Wk : Wv);
    float* Cout = (wz == 0) ? g_q : ((wz == 1) ? g_k : g_v);

    const int r  = tid & 63;
    const int kc = tid >> 6;
    const int ty = tid >> 4;
    const int tx = tid & 15;

    u64 acc2[4][2];
    #pragma unroll
    for (int i = 0; i < 4; ++i) { acc2[i][0] = 0ull; acc2[i][1] = 0ull; }

    const float* Arow = A + (size_t)(bm * 64 + r) * 128;
    const float* Wrow = W + (size_t)(bn * 64 + r) * 128;

    float4 pa[4], pb[4];
    #pragma unroll
    for (int i = 0; i < 4; ++i) {
        const int k0 = kc * 16 + i * 4;
        pa[i] = *(const float4*)&Arow[k0];
        pb[i] = *(const float4*)&Wrow[k0];
    }

    #pragma unroll
    for (int ch = 0; ch < 2; ++ch) {
        #pragma unroll
        for (int i = 0; i < 4; ++i) {
            const int k0 = kc * 16 + i * 4;
            As[k0 + 0][r] = pa[i].x; As[k0 + 1][r] = pa[i].y;
            As[k0 + 2][r] = pa[i].z; As[k0 + 3][r] = pa[i].w;
            Bs[k0 + 0][r] = pb[i].x; Bs[k0 + 1][r] = pb[i].y;
            Bs[k0 + 2][r] = pb[i].z; Bs[k0 + 3][r] = pb[i].w;
        }
        __syncthreads();
        if (ch == 0) {
            #pragma unroll
            for (int i = 0; i < 4; ++i) {
                const int k0 = 64 + kc * 16 + i * 4;
                pa[i] = *(const float4*)&Arow[k0];
                pb[i] = *(const float4*)&Wrow[k0];
            }
        }
        #pragma unroll
        for (int k = 0; k < 64; ++k) {
            float4 a4 = *(const float4*)&As[k][ty * 4];
            ulonglong2 b2 = *(const ulonglong2*)&Bs[k][tx * 4];
            u64 a0 = pack2(a4.x, a4.x);
            u64 a1 = pack2(a4.y, a4.y);
            u64 a2 = pack2(a4.z, a4.z);
            u64 a3 = pack2(a4.w, a4.w);
            acc2[0][0] = fma2(a0, b2.x, acc2[0][0]);
            acc2[0][1] = fma2(a0, b2.y, acc2[0][1]);
            acc2[1][0] = fma2(a1, b2.x, acc2[1][0]);
            acc2[1][1] = fma2(a1, b2.y, acc2[1][1]);
            acc2[2][0] = fma2(a2, b2.x, acc2[2][0]);
            acc2[2][1] = fma2(a2, b2.y, acc2[2][1]);
            acc2[3][0] = fma2(a3, b2.x, acc2[3][0]);
            acc2[3][1] = fma2(a3, b2.y, acc2[3][1]);
        }
        __syncthreads();
    }

    #pragma unroll
    for (int i = 0; i < 4; ++i) {
        const int row = bm * 64 + ty * 4 + i;
        const int b = row >> 11;
        const int s = row & 2047;
        float c[4];
        unpack2(acc2[i][0], c[0], c[1]);
        unpack2(acc2[i][1], c[2], c[3]);
        #pragma unroll
        for (int j = 0; j < 4; ++j) {
            const int col = bn * 64 + tx * 4 + j;
            const int h = col >> 4;
            const int d = col & 15;
            Cout[(((size_t)b * Hq + h) * Sq + s) * HSq + d] = c[j];
        }
    }
}

// ---------------------------------------------------------------------------
// Flash attention per (b,h): one thread per query, 256 queries/block.
// K tile stored key-pair-interleaved: Kt[jp][d] = (K[2jp][d], K[2jp+1][d]),
// so one FFMA2 chain yields two key scores with no horizontal reduction.
// Scores in log2 domain (QSCALE folded into q); exp via ex2.approx.
// grid (S/256, B*H), 256 threads.
// ---------------------------------------------------------------------------
__global__ __launch_bounds__(256) void attn_kernel()
{
    __shared__ float Kt[16 * 32];   // [jp][d][pair], row = 32 floats = 128B
    __shared__ float Vs[32][16];

    const int tid = threadIdx.x;
    const int bh = blockIdx.y;
    const int s = blockIdx.x * 256 + tid;

    const float* qp = &g_q[((size_t)bh * Sq + s) * HSq];
    u64 qd2[16];   // (q[d], q[d]) duplicated
    #pragma unroll
    for (int i = 0; i < 4; ++i) {
        float4 v = *(const float4*)&qp[i * 4];
        qd2[i * 4 + 0] = pack2(v.x * QSCALE, v.x * QSCALE);
        qd2[i * 4 + 1] = pack2(v.y * QSCALE, v.y * QSCALE);
        qd2[i * 4 + 2] = pack2(v.z * QSCALE, v.z * QSCALE);
        qd2[i * 4 + 3] = pack2(v.w * QSCALE, v.w * QSCALE);
    }
    u64 o2[8];
    #pragma unroll
    for (int i = 0; i < 8; ++i) o2[i] = 0ull;

    float m = -INFINITY;
    u64 l2 = 0ull;

    const float4* Kg = (const float4*)&g_k[(size_t)bh * Sq * HSq];
    const float4* Vg = (const float4*)&g_v[(size_t)bh * Sq * HSq];
    float4* Vs4 = (float4*)Vs;

    // loader roles: tid<128 -> K, else V. Each owns one float4 per tile.
    const int lj  = tid >> 2;          // key index 0..31 (K loaders)
    const int ld0 = (tid & 3) * 4;     // dim start
    const int ljp = lj >> 1;
    const int lpar = lj & 1;

    float4 pf = (tid < 128) ? Kg[tid] : Vg[tid - 128];

    for (int kt = 0; kt < Sq / 32; ++kt) {
        if (tid < 128) {
            float* dst = &Kt[ljp * 32 + ld0 * 2 + lpar];
            dst[0] = pf.x; dst[2] = pf.y; dst[4] = pf.z; dst[6] = pf.w;
        } else {
            Vs4[tid - 128] = pf;
        }
        __syncthreads();
        if (kt + 1 < Sq / 32) {
            pf = (tid < 128) ? Kg[(kt + 1) * 128 + tid]
                             : Vg[(kt + 1) * 128 + (tid - 128)];
        }

        // --- scores: 16 key-pairs, packed over keys ---
        u64 sc2[16];
        float tmax = -INFINITY;
        #pragma unroll
        for (int jp = 0; jp < 16; ++jp) {
            const ulonglong2* kp = (const ulonglong2*)&Kt[jp * 32];
            ulonglong2 k0 = kp[0], k1 = kp[1], k2 = kp[2], k3 = kp[3];
            ulonglong2 k4 = kp[4], k5 = kp[5], k6 = kp[6], k7 = kp[7];
            u64 acc = fma2(qd2[0], k0.x, 0ull);
            acc = fma2(qd2[1],  k0.y, acc);
            acc = fma2(qd2[2],  k1.x, acc);
            acc = fma2(qd2[3],  k1.y, acc);
            acc = fma2(qd2[4],  k2.x, acc);
            acc = fma2(qd2[5],  k2.y, acc);
            acc = fma2(qd2[6],  k3.x, acc);
            acc = fma2(qd2[7],  k3.y, acc);
            acc = fma2(qd2[8],  k4.x, acc);
            acc = fma2(qd2[9],  k4.y, acc);
            acc = fma2(qd2[10], k5.x, acc);
            acc = fma2(qd2[11], k5.y, acc);
            acc = fma2(qd2[12], k6.x, acc);
            acc = fma2(qd2[13], k6.y, acc);
            acc = fma2(qd2[14], k7.x, acc);
            acc = fma2(qd2[15], k7.y, acc);
            sc2[jp] = acc;
            float s0, s1;
            unpack2(acc, s0, s1);
            tmax = fmaxf(tmax, fmaxf(s0, s1));
        }

        const float mnew = fmaxf(m, tmax);
        const float corr = ex2(m - mnew);   // ex2(-inf)=0 handles first tile
        const u64 corr2 = pack2(corr, corr);
        l2 = mul2(corr2, l2);
        #pragma unroll
        for (int i = 0; i < 8; ++i) o2[i] = mul2(corr2, o2[i]);

        #pragma unroll
        for (int jp = 0; jp < 16; ++jp) {
            float s0, s1;
            unpack2(sc2[jp], s0, s1);
            const float p0 = ex2(s0 - mnew);
            const float p1 = ex2(s1 - mnew);
            l2 = add2(l2, pack2(p0, p1));
            const u64 pa = pack2(p0, p0);
            const u64 pb = pack2(p1, p1);
            const ulonglong2* va = (const ulonglong2*)&Vs[2 * jp][0];
            ulonglong2 va0 = va[0], va1 = va[1], va2 = va[2], va3 = va[3];
            o2[0] = fma2(pa, va0.x, o2[0]);
            o2[1] = fma2(pa, va0.y, o2[1]);
            o2[2] = fma2(pa, va1.x, o2[2]);
            o2[3] = fma2(pa, va1.y, o2[3]);
            o2[4] = fma2(pa, va2.x, o2[4]);
            o2[5] = fma2(pa, va2.y, o2[5]);
            o2[6] = fma2(pa, va3.x, o2[6]);
            o2[7] = fma2(pa, va3.y, o2[7]);
            const ulonglong2* vb = (const ulonglong2*)&Vs[2 * jp + 1][0];
            ulonglong2 vb0 = vb[0], vb1 = vb[1], vb2 = vb[2], vb3 = vb[3];
            o2[0] = fma2(pb, vb0.x, o2[0]);
            o2[1] = fma2(pb, vb0.y, o2[1]);
            o2[2] = fma2(pb, vb1.x, o2[2]);
            o2[3] = fma2(pb, vb1.y, o2[3]);
            o2[4] = fma2(pb, vb2.x, o2[4]);
            o2[5] = fma2(pb, vb2.y, o2[5]);
            o2[6] = fma2(pb, vb3.x, o2[6]);
            o2[7] = fma2(pb, vb3.y, o2[7]);
        }
        m = mnew;
        __syncthreads();
    }

    float la, lb;
    unpack2(l2, la, lb);
    const float inv = 1.0f / (la + lb);
    const int b = bh >> 3;
    const int h = bh & 7;
    float* op = &g_a[((size_t)b * Sq + s) * Eq + h * HSq];
    #pragma unroll
    for (int i = 0; i < 4; ++i) {
        float a0, a1, a2, a3;
        unpack2(o2[i * 2 + 0], a0, a1);
        unpack2(o2[i * 2 + 1], a2, a3);
        float4 v;
        v.x = a0 * inv; v.y = a1 * inv; v.z = a2 * inv; v.w = a3 * inv;
        *(float4*)&op[i * 4] = v;
    }
}

// ---------------------------------------------------------------------------
// Output projection, f32x2-packed mainloop + prefetch. grid (256, 2).
// ---------------------------------------------------------------------------
__global__ __launch_bounds__(256) void proj_gemm(
    const float* __restrict__ W,
    const float* __restrict__ bias,
    float* __restrict__ C)
{
    __shared__ float As[64][68];
    __shared__ float Bs[64][68];

    const int tid = threadIdx.x;
    const int bm = blockIdx.x;
    const int bn = blockIdx.y;

    const int r  = tid & 63;
    const int kc = tid >> 6;
    const int ty = tid >> 4;
    const int tx = tid & 15;

    u64 acc2[4][2];
    #pragma unroll
    for (int i = 0; i < 4; ++i) { acc2[i][0] = 0ull; acc2[i][1] = 0ull; }

    const float* Arow = g_a + (size_t)(bm * 64 + r) * 128;
    const float* Wrow = W + (size_t)(bn * 64 + r) * 128;

    float4 pa[4], pb[4];
    #pragma unroll
    for (int i = 0; i < 4; ++i) {
        const int k0 = kc * 16 + i * 4;
        pa[i] = *(const float4*)&Arow[k0];
        pb[i] = *(const float4*)&Wrow[k0];
    }

    #pragma unroll
    for (int ch = 0; ch < 2; ++ch) {
        #pragma unroll
        for (int i = 0; i < 4; ++i) {
            const int k0 = kc * 16 + i * 4;
            As[k0 + 0][r] = pa[i].x; As[k0 + 1][r] = pa[i].y;
            As[k0 + 2][r] = pa[i].z; As[k0 + 3][r] = pa[i].w;
            Bs[k0 + 0][r] = pb[i].x; Bs[k0 + 1][r] = pb[i].y;
            Bs[k0 + 2][r] = pb[i].z; Bs[k0 + 3][r] = pb[i].w;
        }
        __syncthreads();
        if (ch == 0) {
            #pragma unroll
            for (int i = 0; i < 4; ++i) {
                const int k0 = 64 + kc * 16 + i * 4;
                pa[i] = *(const float4*)&Arow[k0];
                pb[i] = *(const float4*)&Wrow[k0];
            }
        }
        #pragma unroll
        for (int k = 0; k < 64; ++k) {
            float4 a4 = *(const float4*)&As[k][ty * 4];
            ulonglong2 b2 = *(const ulonglong2*)&Bs[k][tx * 4];
            u64 a0 = pack2(a4.x, a4.x);
            u64 a1 = pack2(a4.y, a4.y);
            u64 a2 = pack2(a4.z, a4.z);
            u64 a3 = pack2(a4.w, a4.w);
            acc2[0][0] = fma2(a0, b2.x, acc2[0][0]);
            acc2[0][1] = fma2(a0, b2.y, acc2[0][1]);
            acc2[1][0] = fma2(a1, b2.x, acc2[1][0]);
            acc2[1][1] = fma2(a1, b2.y, acc2[1][1]);
            acc2[2][0] = fma2(a2, b2.x, acc2[2][0]);
            acc2[2][1] = fma2(a2, b2.y, acc2[2][1]);
            acc2[3][0] = fma2(a3, b2.x, acc2[3][0]);
            acc2[3][1] = fma2(a3, b2.y, acc2[3][1]);
        }
        __syncthreads();
    }

    #pragma unroll
    for (int i = 0; i < 4; ++i) {
        const int row = bm * 64 + ty * 4 + i;
        float c[4];
        unpack2(acc2[i][0], c[0], c[1]);
        unpack2(acc2[i][1], c[2], c[3]);
        #pragma unroll
        for (int j = 0; j < 4; ++j) {
            const int col = bn * 64 + tx * 4 + j;
            C[(size_t)row * Eq + col] = c[j] + bias[col];
        }
    }
}

// ---------------------------------------------------------------------------
// Launch. Inputs (metadata order): x, Wk, Wq, Wv, Wp, bp. Output: float32.
// ---------------------------------------------------------------------------
extern "C" void kernel_launch(void* const* d_in, const int* in_sizes, int n_in,
                              void* d_out, int out_size)
{
    const float* x  = (const float*)d_in[0];
    const float* Wk = (const float*)d_in[1];
    const float* Wq = (const float*)d_in[2];
    const float* Wv = (const float*)d_in[3];
    const float* Wp = (const float*)d_in[4];
    const float* bp = (const float*)d_in[5];
    float* out = (float*)d_out;

    qkv_gemm<<<dim3(BSROWS / 64, 2, 3), 256>>>(x, Wq, Wk, Wv);
    attn_kernel<<<dim3(Sq / 256, Bq * Hq), 256>>>();
    proj_gemm<<<dim3(BSROWS / 64, 2), 256>>>(Wp, bp, out);
}

// round 6
// speedup vs baseline: 3.7224x; 2.3337x over previous
#include <cuda_runtime.h>
#include <cuda_bf16.h>
#include <math.h>
#include <stdint.h>

#define Bq 8
#define Sq 2048
#define Eq 128
#define Hq 8
#define HSq 16
#define BSROWS (Bq * Sq)
#define NBH 64
#define NT 16

typedef unsigned long long u64;
typedef unsigned int u32;

#define QSCALE 5.770780163555854f   // 4 * log2(e), folded into Q

// ---- packed f32x2 helpers (scalar GEMMs) ----
__device__ __forceinline__ u64 pack2(float lo, float hi) {
    u64 r; asm("mov.b64 %0, {%1,%2};" : "=l"(r) : "f"(lo), "f"(hi)); return r;
}
__device__ __forceinline__ u64 fma2(u64 a, u64 b, u64 c) {
    u64 d; asm("fma.rn.f32x2 %0, %1, %2, %3;" : "=l"(d) : "l"(a), "l"(b), "l"(c)); return d;
}
__device__ __forceinline__ void unpack2(u64 v, float& lo, float& hi) {
    asm("mov.b64 {%0,%1}, %2;" : "=f"(lo), "=f"(hi) : "l"(v));
}
__device__ __forceinline__ float ex2f(float x) {
    float y; asm("ex2.approx.f32 %0, %1;" : "=f"(y) : "f"(x)); return y;
}
__device__ __forceinline__ u32 cvt_bf16x2(float even, float odd) {
    u32 r; asm("cvt.rn.satfinite.bf16x2.f32 %0, %1, %2;" : "=r"(r) : "f"(odd), "f"(even));
    return r;  // low half = even
}
// bf16 HMMA (sm_80+ base-target safe)
__device__ __forceinline__ void mma_bf16(float* c, const u32* a, u32 b0, u32 b1) {
    asm volatile("mma.sync.aligned.m16n8k16.row.col.f32.bf16.bf16.f32 "
                 "{%0,%1,%2,%3}, {%4,%5,%6,%7}, {%8,%9}, {%0,%1,%2,%3};"
                 : "+f"(c[0]), "+f"(c[1]), "+f"(c[2]), "+f"(c[3])
                 : "r"(a[0]), "r"(a[1]), "r"(a[2]), "r"(a[3]), "r"(b0), "r"(b1));
}

// Scratch (device globals). bf16 data stored inside u32 arrays for alignment.
__device__ __align__(16) u32 g_qh[NBH * Sq * 8];   // Q hi: [bh][s][16 bf16], QSCALE folded
__device__ __align__(16) u32 g_ql[NBH * Sq * 8];   // Q lo
__device__ __align__(16) u32 g_kh[NBH * Sq * 8];   // K hi
__device__ __align__(16) u32 g_kl[NBH * Sq * 8];   // K lo
__device__ __align__(16) u32 g_vh[NBH * (Sq/2) * 16];  // V hi paired: [bh][s/2][d][2]
__device__ __align__(16) u32 g_vl[NBH * (Sq/2) * 16];  // V lo paired
__device__ float g_a[BSROWS * Eq];

// ---------------------------------------------------------------------------
// QKV GEMM (fp32 FFMA2 mainloop); epilogue emits split-bf16 HMMA layouts.
// ---------------------------------------------------------------------------
__global__ __launch_bounds__(256) void qkv_gemm(
    const float* __restrict__ A, const float* __restrict__ Wq,
    const float* __restrict__ Wk, const float* __restrict__ Wv)
{
    __shared__ float As[64][68];
    __shared__ float Bs[64][68];

    const int tid = threadIdx.x, bm = blockIdx.x, bn = blockIdx.y, wz = blockIdx.z;
    const float* W = (wz == 0) ? Wq : ((wz == 1) ? Wk : Wv);
    const int r = tid & 63, kc = tid >> 6, ty = tid >> 4, tx = tid & 15;

    u64 acc2[4][2];
    #pragma unroll
    for (int i = 0; i < 4; ++i) { acc2[i][0] = 0ull; acc2[i][1] = 0ull; }

    const float* Arow = A + (size_t)(bm * 64 + r) * 128;
    const float* Wrow = W + (size_t)(bn * 64 + r) * 128;

    float4 pa[4], pb[4];
    #pragma unroll
    for (int i = 0; i < 4; ++i) {
        const int k0 = kc * 16 + i * 4;
        pa[i] = *(const float4*)&Arow[k0];
        pb[i] = *(const float4*)&Wrow[k0];
    }
    #pragma unroll
    for (int ch = 0; ch < 2; ++ch) {
        #pragma unroll
        for (int i = 0; i < 4; ++i) {
            const int k0 = kc * 16 + i * 4;
            As[k0+0][r] = pa[i].x; As[k0+1][r] = pa[i].y; As[k0+2][r] = pa[i].z; As[k0+3][r] = pa[i].w;
            Bs[k0+0][r] = pb[i].x; Bs[k0+1][r] = pb[i].y; Bs[k0+2][r] = pb[i].z; Bs[k0+3][r] = pb[i].w;
        }
        __syncthreads();
        if (ch == 0) {
            #pragma unroll
            for (int i = 0; i < 4; ++i) {
                const int k0 = 64 + kc * 16 + i * 4;
                pa[i] = *(const float4*)&Arow[k0];
                pb[i] = *(const float4*)&Wrow[k0];
            }
        }
        #pragma unroll
        for (int k = 0; k < 64; ++k) {
            float4 a4 = *(const float4*)&As[k][ty * 4];
            ulonglong2 b2 = *(const ulonglong2*)&Bs[k][tx * 4];
            u64 a0 = pack2(a4.x, a4.x), a1 = pack2(a4.y, a4.y);
            u64 a2 = pack2(a4.z, a4.z), a3 = pack2(a4.w, a4.w);
            acc2[0][0] = fma2(a0, b2.x, acc2[0][0]); acc2[0][1] = fma2(a0, b2.y, acc2[0][1]);
            acc2[1][0] = fma2(a1, b2.x, acc2[1][0]); acc2[1][1] = fma2(a1, b2.y, acc2[1][1]);
            acc2[2][0] = fma2(a2, b2.x, acc2[2][0]); acc2[2][1] = fma2(a2, b2.y, acc2[2][1]);
            acc2[3][0] = fma2(a3, b2.x, acc2[3][0]); acc2[3][1] = fma2(a3, b2.y, acc2[3][1]);
        }
        __syncthreads();
    }

    __nv_bfloat16* qh = (__nv_bfloat16*)g_qh;
    __nv_bfloat16* ql = (__nv_bfloat16*)g_ql;
    __nv_bfloat16* kh = (__nv_bfloat16*)g_kh;
    __nv_bfloat16* kl = (__nv_bfloat16*)g_kl;
    __nv_bfloat16* vh = (__nv_bfloat16*)g_vh;
    __nv_bfloat16* vl = (__nv_bfloat16*)g_vl;

    #pragma unroll
    for (int i = 0; i < 4; ++i) {
        const int row = bm * 64 + ty * 4 + i;
        const int b = row >> 11, s = row & 2047;
        float c[4];
        unpack2(acc2[i][0], c[0], c[1]);
        unpack2(acc2[i][1], c[2], c[3]);
        #pragma unroll
        for (int j = 0; j < 4; ++j) {
            const int col = bn * 64 + tx * 4 + j;
            const int h = col >> 4, d = col & 15;
            const int bh = b * Hq + h;
            float x = (wz == 0) ? c[j] * QSCALE : c[j];
            __nv_bfloat16 hi = __float2bfloat16(x);
            __nv_bfloat16 lo = __float2bfloat16(x - __bfloat162float(hi));
            if (wz == 2) {
                size_t idx = (((size_t)bh * (Sq/2) + (s >> 1)) * 16 + d) * 2 + (s & 1);
                vh[idx] = hi; vl[idx] = lo;
            } else if (wz == 0) {
                size_t idx = ((size_t)bh * Sq + s) * 16 + d;
                qh[idx] = hi; ql[idx] = lo;
            } else {
                size_t idx = ((size_t)bh * Sq + s) * 16 + d;
                kh[idx] = hi; kl[idx] = lo;
            }
        }
    }
}

// ---------------------------------------------------------------------------
// HMMA flash attention. CTA = 128 queries of one (b,h), 256 threads = 8 warps,
// each warp owns 16 query rows. Key tiles of 128, double-buffered in smem.
//   QK:  3x mma (Qhi*Khi + Qlo*Khi + Qhi*Klo), scores fp32 in C frags
//   softmax: register fragments + quad shuffles, ex2.approx
//   PV:  P(bf16) x [Vhi | Vlo | ones-col] -> o frags + l via ones column
// grid (16, 64).
// ---------------------------------------------------------------------------
__global__ __launch_bounds__(256) void attn_mma()
{
    __shared__ __align__(16) u32 sK[2][2][1024];  // [buf][hi/lo][key*8 + c]
    __shared__ __align__(16) u32 sV[2][2][1024];  // [buf][hi/lo][pair*16 + d]

    const int tid = threadIdx.x;
    const int lane = tid & 31, wid = tid >> 5;
    const int g = lane >> 2, c = lane & 3;
    const int bh = blockIdx.y;
    const int q0 = blockIdx.x * 128;
    const int rowbase = q0 + wid * 16;

    // Q fragments (A, m16k16): a0=row g cols 2c..; a1=row g+8; a2/a3 = +8 cols
    u32 qh[4], qlo[4];
    {
        const u32* ph = g_qh + ((size_t)bh * Sq + rowbase) * 8;
        const u32* pl = g_ql + ((size_t)bh * Sq + rowbase) * 8;
        qh[0] = ph[g * 8 + c];       qh[1] = ph[(g + 8) * 8 + c];
        qh[2] = ph[g * 8 + c + 4];   qh[3] = ph[(g + 8) * 8 + c + 4];
        qlo[0] = pl[g * 8 + c];      qlo[1] = pl[(g + 8) * 8 + c];
        qlo[2] = pl[g * 8 + c + 4];  qlo[3] = pl[(g + 8) * 8 + c + 4];
    }

    float o[3][4];   // n-tiles: dims 0-7, dims 8-15, l (ones col)
    #pragma unroll
    for (int n = 0; n < 3; ++n)
        #pragma unroll
        for (int i = 0; i < 4; ++i) o[n][i] = 0.0f;
    float m0 = -INFINITY, m1 = -INFINITY;

    const u32 b_one = (g == 0) ? 0x3F803F80u : 0u;  // ones column (dim16)

    // tile sources: 256 float4 per array per tile; thread owns index tid
    const float4* skh = (const float4*)(g_kh + (size_t)bh * Sq * 8) + tid;
    const float4* skl = (const float4*)(g_kl + (size_t)bh * Sq * 8) + tid;
    const float4* svh = (const float4*)(g_vh + (size_t)bh * (Sq/2) * 16) + tid;
    const float4* svl = (const float4*)(g_vl + (size_t)bh * (Sq/2) * 16) + tid;

    float4 pkh = skh[0], pkl = skl[0], pvh = svh[0], pvl = svl[0];

    for (int kt = 0; kt < NT; ++kt) {
        const int buf = kt & 1;
        ((float4*)sK[buf][0])[tid] = pkh;
        ((float4*)sK[buf][1])[tid] = pkl;
        ((float4*)sV[buf][0])[tid] = pvh;
        ((float4*)sV[buf][1])[tid] = pvl;
        __syncthreads();
        if (kt + 1 < NT) {
            pkh = skh[(kt + 1) * 256];
            pkl = skl[(kt + 1) * 256];
            pvh = svh[(kt + 1) * 256];
            pvl = svl[(kt + 1) * 256];
        }

        // ---- QK scores: 16 n-tiles of 8 keys ----
        float sc[16][4];
        #pragma unroll
        for (int n = 0; n < 16; ++n) {
            sc[n][0] = sc[n][1] = sc[n][2] = sc[n][3] = 0.0f;
            const int key = n * 8 + g;
            const u32 kh0 = sK[buf][0][key * 8 + c];
            const u32 kh1 = sK[buf][0][key * 8 + c + 4];
            const u32 kl0 = sK[buf][1][key * 8 + c];
            const u32 kl1 = sK[buf][1][key * 8 + c + 4];
            mma_bf16(sc[n], qh, kh0, kh1);
            mma_bf16(sc[n], qlo, kh0, kh1);
            mma_bf16(sc[n], qh, kl0, kl1);
        }

        // ---- row max (rows g and g+8), quad reduction over c ----
        float mx0 = sc[0][0], mx1 = sc[0][2];
        #pragma unroll
        for (int n = 0; n < 16; ++n) {
            mx0 = fmaxf(mx0, fmaxf(sc[n][0], sc[n][1]));
            mx1 = fmaxf(mx1, fmaxf(sc[n][2], sc[n][3]));
        }
        mx0 = fmaxf(mx0, __shfl_xor_sync(0xffffffffu, mx0, 1));
        mx0 = fmaxf(mx0, __shfl_xor_sync(0xffffffffu, mx0, 2));
        mx1 = fmaxf(mx1, __shfl_xor_sync(0xffffffffu, mx1, 1));
        mx1 = fmaxf(mx1, __shfl_xor_sync(0xffffffffu, mx1, 2));

        const float mn0 = fmaxf(m0, mx0), mn1 = fmaxf(m1, mx1);
        const float cr0 = ex2f(m0 - mn0), cr1 = ex2f(m1 - mn1);
        m0 = mn0; m1 = mn1;

        // ---- exp + convert to P fragments ----
        #pragma unroll
        for (int n = 0; n < 16; ++n) {
            sc[n][0] = ex2f(sc[n][0] - mn0);
            sc[n][1] = ex2f(sc[n][1] - mn0);
            sc[n][2] = ex2f(sc[n][2] - mn1);
            sc[n][3] = ex2f(sc[n][3] - mn1);
        }
        u32 pf[8][4];
        #pragma unroll
        for (int kk = 0; kk < 8; ++kk) {
            pf[kk][0] = cvt_bf16x2(sc[2*kk][0],   sc[2*kk][1]);
            pf[kk][1] = cvt_bf16x2(sc[2*kk][2],   sc[2*kk][3]);
            pf[kk][2] = cvt_bf16x2(sc[2*kk+1][0], sc[2*kk+1][1]);
            pf[kk][3] = cvt_bf16x2(sc[2*kk+1][2], sc[2*kk+1][3]);
        }

        // ---- rescale o by corr ----
        #pragma unroll
        for (int n = 0; n < 3; ++n) {
            o[n][0] *= cr0; o[n][1] *= cr0;
            o[n][2] *= cr1; o[n][3] *= cr1;
        }

        // ---- PV: 8 k-tiles of 16 keys ----
        #pragma unroll
        for (int kk = 0; kk < 8; ++kk) {
            const int p0 = kk * 8 + c;
            const u32 vh00 = sV[buf][0][p0 * 16 + g];
            const u32 vh01 = sV[buf][0][(p0 + 4) * 16 + g];
            const u32 vh10 = sV[buf][0][p0 * 16 + 8 + g];
            const u32 vh11 = sV[buf][0][(p0 + 4) * 16 + 8 + g];
            const u32 vl00 = sV[buf][1][p0 * 16 + g];
            const u32 vl01 = sV[buf][1][(p0 + 4) * 16 + g];
            const u32 vl10 = sV[buf][1][p0 * 16 + 8 + g];
            const u32 vl11 = sV[buf][1][(p0 + 4) * 16 + 8 + g];
            mma_bf16(o[0], pf[kk], vh00, vh01);
            mma_bf16(o[1], pf[kk], vh10, vh11);
            mma_bf16(o[0], pf[kk], vl00, vl01);
            mma_bf16(o[1], pf[kk], vl10, vl11);
            mma_bf16(o[2], pf[kk], b_one, b_one);
        }
        __syncthreads();
    }

    // ---- normalize and store ----
    const float l0 = __shfl_sync(0xffffffffu, o[2][0], lane & ~3);
    const float l1 = __shfl_sync(0xffffffffu, o[2][2], lane & ~3);
    const float i0 = 1.0f / l0, i1 = 1.0f / l1;
    const int b = bh >> 3, h = bh & 7;
    const int s0 = rowbase + g, s1 = rowbase + g + 8;
    #pragma unroll
    for (int n = 0; n < 2; ++n) {
        const int col = h * 16 + n * 8 + 2 * c;
        float2 v0 = make_float2(o[n][0] * i0, o[n][1] * i0);
        float2 v1 = make_float2(o[n][2] * i1, o[n][3] * i1);
        *(float2*)&g_a[((size_t)b * Sq + s0) * Eq + col] = v0;
        *(float2*)&g_a[((size_t)b * Sq + s1) * Eq + col] = v1;
    }
}

// ---------------------------------------------------------------------------
// Output projection (unchanged). grid (256, 2).
// ---------------------------------------------------------------------------
__global__ __launch_bounds__(256) void proj_gemm(
    const float* __restrict__ W, const float* __restrict__ bias, float* __restrict__ C)
{
    __shared__ float As[64][68];
    __shared__ float Bs[64][68];

    const int tid = threadIdx.x, bm = blockIdx.x, bn = blockIdx.y;
    const int r = tid & 63, kc = tid >> 6, ty = tid >> 4, tx = tid & 15;

    u64 acc2[4][2];
    #pragma unroll
    for (int i = 0; i < 4; ++i) { acc2[i][0] = 0ull; acc2[i][1] = 0ull; }

    const float* Arow = g_a + (size_t)(bm * 64 + r) * 128;
    const float* Wrow = W + (size_t)(bn * 64 + r) * 128;

    float4 pa[4], pb[4];
    #pragma unroll
    for (int i = 0; i < 4; ++i) {
        const int k0 = kc * 16 + i * 4;
        pa[i] = *(const float4*)&Arow[k0];
        pb[i] = *(const float4*)&Wrow[k0];
    }
    #pragma unroll
    for (int ch = 0; ch < 2; ++ch) {
        #pragma unroll
        for (int i = 0; i < 4; ++i) {
            const int k0 = kc * 16 + i * 4;
            As[k0+0][r] = pa[i].x; As[k0+1][r] = pa[i].y; As[k0+2][r] = pa[i].z; As[k0+3][r] = pa[i].w;
            Bs[k0+0][r] = pb[i].x; Bs[k0+1][r] = pb[i].y; Bs[k0+2][r] = pb[i].z; Bs[k0+3][r] = pb[i].w;
        }
        __syncthreads();
        if (ch == 0) {
            #pragma unroll
            for (int i = 0; i < 4; ++i) {
                const int k0 = 64 + kc * 16 + i * 4;
                pa[i] = *(const float4*)&Arow[k0];
                pb[i] = *(const float4*)&Wrow[k0];
            }
        }
        #pragma unroll
        for (int k = 0; k < 64; ++k) {
            float4 a4 = *(const float4*)&As[k][ty * 4];
            ulonglong2 b2 = *(const ulonglong2*)&Bs[k][tx * 4];
            u64 a0 = pack2(a4.x, a4.x), a1 = pack2(a4.y, a4.y);
            u64 a2 = pack2(a4.z, a4.z), a3 = pack2(a4.w, a4.w);
            acc2[0][0] = fma2(a0, b2.x, acc2[0][0]); acc2[0][1] = fma2(a0, b2.y, acc2[0][1]);
            acc2[1][0] = fma2(a1, b2.x, acc2[1][0]); acc2[1][1] = fma2(a1, b2.y, acc2[1][1]);
            acc2[2][0] = fma2(a2, b2.x, acc2[2][0]); acc2[2][1] = fma2(a2, b2.y, acc2[2][1]);
            acc2[3][0] = fma2(a3, b2.x, acc2[3][0]); acc2[3][1] = fma2(a3, b2.y, acc2[3][1]);
        }
        __syncthreads();
    }
    #pragma unroll
    for (int i = 0; i < 4; ++i) {
        const int row = bm * 64 + ty * 4 + i;
        float c[4];
        unpack2(acc2[i][0], c[0], c[1]);
        unpack2(acc2[i][1], c[2], c[3]);
        #pragma unroll
        for (int j = 0; j < 4; ++j) {
            const int col = bn * 64 + tx * 4 + j;
            C[(size_t)row * Eq + col] = c[j] + bias[col];
        }
    }
}

// ---------------------------------------------------------------------------
// Launch. Inputs: x, Wk, Wq, Wv, Wp, bp. Output: float32.
// ---------------------------------------------------------------------------
extern "C" void kernel_launch(void* const* d_in, const int* in_sizes, int n_in,
                              void* d_out, int out_size)
{
    const float* x  = (const float*)d_in[0];
    const float* Wk = (const float*)d_in[1];
    const float* Wq = (const float*)d_in[2];
    const float* Wv = (const float*)d_in[3];
    const float* Wp = (const float*)d_in[4];
    const float* bp = (const float*)d_in[5];
    float* out = (float*)d_out;

    qkv_gemm<<<dim3(BSROWS / 64, 2, 3), 256>>>(x, Wq, Wk, Wv);
    attn_mma<<<dim3(Sq / 128, NBH), 256>>>();
    proj_gemm<<<dim3(BSROWS / 64, 2), 256>>>(Wp, bp, out);
}